// round 17
// baseline (speedup 1.0000x reference)
#include <cuda_runtime.h>
#include <cuda_fp16.h>
#include <cstdint>

#define T_TOK 16384
#define HID   2048
#define IEXP  1024
#define NEXP  8
#define VOCAB_SZ 100000
#define TPE   12500

#define BM 192
#define BK 32
#define STRA 40                       // A row stride (halfs): 80B aligned, conflict-free
#define AH (BM * STRA)                // 7680 halfs / stage
#define BSTR 264                      // 256n + 8 pad halfs; 528B row, conflict-free (validated R15)
#define BH (BK * BSTR)                // 8448 halfs
#define STGH (AH + BH)                // 16128 halfs = 32256 B / stage
#define NST 4
#define TOKS_OFF (NST * STGH * 2)     // 129024 B
#define SMB (TOKS_OFF + BM * 4 + 64)  // ~129.8 KB -> 1 CTA/SM

#define HSW 132                       // gate-exchange fp32 stride

__device__ __half x_h [(size_t)T_TOK * HID];
__device__ __half h_h [(size_t)T_TOK * IEXP];
__device__ __half gw_h[(size_t)NEXP * HID * IEXP];
__device__ __half uw_h[(size_t)NEXP * HID * IEXP];
__device__ __half dw_h[(size_t)NEXP * IEXP * HID];
__device__ int    perm_d[T_TOK];
__device__ int    cnt_d[NEXP];
__device__ int    base_d[NEXP];

__global__ void k_route(const int* __restrict__ ids) {
    __shared__ int c[NEXP], b[NEXP], cu[NEXP];
    int t = threadIdx.x;
    if (t < NEXP) { c[t] = 0; cu[t] = 0; }
    __syncthreads();
    for (int i = t; i < T_TOK; i += 256) {
        int v = ids[i]; v = max(0, min(v, VOCAB_SZ - 1));
        atomicAdd(&c[min(v / TPE, NEXP - 1)], 1);
    }
    __syncthreads();
    if (t == 0) { int s = 0; for (int e = 0; e < NEXP; e++) { b[e] = s; s += c[e]; } }
    __syncthreads();
    for (int i = t; i < T_TOK; i += 256) {
        int v = ids[i]; v = max(0, min(v, VOCAB_SZ - 1));
        int e = min(v / TPE, NEXP - 1);
        perm_d[b[e] + atomicAdd(&cu[e], 1)] = i;
    }
    if (t < NEXP) { cnt_d[t] = c[t]; base_d[t] = b[t]; }
}

__global__ void k_prep(const float* __restrict__ X) {
    size_t i = ((size_t)blockIdx.x * blockDim.x + threadIdx.x) * 8;
    float4 v0 = *(const float4*)(X + i);
    float4 v1 = *(const float4*)(X + i + 4);
    __half2 h0 = __floats2half2_rn(v0.x, v0.y), h1 = __floats2half2_rn(v0.z, v0.w);
    __half2 h2 = __floats2half2_rn(v1.x, v1.y), h3 = __floats2half2_rn(v1.z, v1.w);
    uint4 w = make_uint4(*(unsigned*)&h0, *(unsigned*)&h1, *(unsigned*)&h2, *(unsigned*)&h3);
    *(uint4*)(x_h + i) = w;
}

__global__ void k_wconv(const float* __restrict__ G, const float* __restrict__ U,
                        const float* __restrict__ D) {
    const float* src = (blockIdx.y == 0) ? G : (blockIdx.y == 1) ? U : D;
    __half* dst = (blockIdx.y == 0) ? gw_h : (blockIdx.y == 1) ? uw_h : dw_h;
    size_t i = ((size_t)blockIdx.x * blockDim.x + threadIdx.x) * 8;
    float4 v0 = *(const float4*)(src + i);
    float4 v1 = *(const float4*)(src + i + 4);
    __half2 h0 = __floats2half2_rn(v0.x, v0.y), h1 = __floats2half2_rn(v0.z, v0.w);
    __half2 h2 = __floats2half2_rn(v1.x, v1.y), h3 = __floats2half2_rn(v1.z, v1.w);
    uint4 w = make_uint4(*(unsigned*)&h0, *(unsigned*)&h1, *(unsigned*)&h2, *(unsigned*)&h3);
    *(uint4*)(dst + i) = w;
}

__device__ __forceinline__ void mma_h(float* c, const unsigned* a, const unsigned* b) {
    asm volatile(
        "mma.sync.aligned.m16n8k16.row.col.f32.f16.f16.f32 "
        "{%0,%1,%2,%3},{%4,%5,%6,%7},{%8,%9},{%0,%1,%2,%3};"
        : "+f"(c[0]), "+f"(c[1]), "+f"(c[2]), "+f"(c[3])
        : "r"(a[0]), "r"(a[1]), "r"(a[2]), "r"(a[3]), "r"(b[0]), "r"(b[1]));
}
__device__ __forceinline__ void cp16(unsigned dst, const void* src) {
    asm volatile("cp.async.cg.shared.global [%0], [%1], 16;" :: "r"(dst), "l"(src));
}
#define CP_COMMIT() asm volatile("cp.async.commit_group;")
#define CP_WAIT2()  asm volatile("cp.async.wait_group 2;")
#define LDSM4(r0, r1, r2, r3, addr)                                             \
    asm volatile("ldmatrix.sync.aligned.m8n8.x4.shared.b16 {%0,%1,%2,%3}, [%4];" \
        : "=r"(r0), "=r"(r1), "=r"(r2), "=r"(r3) : "r"(addr))
#define LDSM4T(r0, r1, r2, r3, addr)                                            \
    asm volatile("ldmatrix.sync.aligned.m8n8.x4.trans.shared.b16 {%0,%1,%2,%3}, [%4];" \
        : "=r"(r0), "=r"(r1), "=r"(r2), "=r"(r3) : "r"(addr))

// warp tile 64m x 64n: per kk, 4 A-LDSM + 4 B-LDSM, 32 MMA
#define GEMM_CHUNK(stOff)                                                       \
    _Pragma("unroll")                                                           \
    for (int kk = 0; kk < 2; kk++) {                                            \
        unsigned af[4][4];                                                      \
        _Pragma("unroll")                                                       \
        for (int mi = 0; mi < 4; mi++)                                          \
            LDSM4(af[mi][0], af[mi][1], af[mi][2], af[mi][3],                   \
                  aLd + (stOff) + mi * (16 * STRA * 2) + kk * 32);              \
        _Pragma("unroll")                                                       \
        for (int p = 0; p < 4; p++) {                                           \
            unsigned b0, b1, b2, b3;                                            \
            LDSM4T(b0, b1, b2, b3,                                              \
                   bLd + (stOff) + kk * (16 * BSTR * 2) + p * 32);              \
            unsigned bf0[2] = { b0, b1 }, bf1[2] = { b2, b3 };                  \
            _Pragma("unroll")                                                   \
            for (int mi = 0; mi < 4; mi++) {                                    \
                mma_h(acc[mi][2 * p],     af[mi], bf0);                         \
                mma_h(acc[mi][2 * p + 1], af[mi], bf1);                         \
            }                                                                   \
        }                                                                       \
    }

// ============== fused gate/up + silu: CTA 192m x (128g + 128u) ==============
__global__ __launch_bounds__(384, 1)
void k_mlp()
{
    extern __shared__ __half smh[];
    int e   = blockIdx.z;
    int cnt = cnt_d[e];
    int m0  = blockIdx.y * BM;
    if (m0 >= cnt) return;
    int n0    = blockIdx.x * 128;
    int valid = min(cnt - m0, BM);
    int pbase = base_d[e] + m0;
    int tid = threadIdx.x, lane = tid & 31, wid = tid >> 5;

    int* toks = (int*)((char*)smh + TOKS_OFF);
    if (tid < BM) toks[tid] = perm_d[pbase + min(tid, valid - 1)];
    __syncthreads();

    // A staging: 2 thr/row x 192 rows, 16 halfs (2 cp16) each
    int arow = tid >> 1, aseg = tid & 1;
    const __half* Ag = x_h + (size_t)toks[arow] * HID + aseg * 16;
    unsigned sb = (unsigned)__cvta_generic_to_shared(smh);
    unsigned aD = sb + (arow * STRA + aseg * 16) * 2;

    // B staging (tid<256): 32 k-rows x 256 combined cols, 32 halfs (4 cp16)/thread
    int brw = (tid & 255) >> 3, bsg = tid & 7;
    int ccol = bsg * 32;
    const __half* Bg = (ccol < 128 ? gw_h : uw_h) + (size_t)e * HID * IEXP
                     + (size_t)brw * IEXP + n0 + (ccol & 127);
    unsigned bD = sb + (AH + brw * BSTR + ccol) * 2;
    bool doB = (tid < 256);

    auto stage = [&](int s, int k0) {
        unsigned off = (unsigned)s * (STGH * 2);
        const __half* as = Ag + k0;
        cp16(aD + off, as);
        cp16(aD + off + 16, as + 8);
        if (doB) {
            const __half* bs = Bg + (size_t)k0 * IEXP;
#pragma unroll
            for (int j = 0; j < 4; j++) cp16(bD + off + j * 16, bs + j * 8);
        }
    };

    float acc[4][8][4];
#pragma unroll
    for (int i = 0; i < 4; i++)
#pragma unroll
        for (int j = 0; j < 8; j++)
#pragma unroll
            for (int k = 0; k < 4; k++) acc[i][j][k] = 0.f;

    int wm = (wid % 3) * 64;              // 3 m-positions
    int wn = (wid / 3) * 64;              // 4 n-positions over combined 256

    unsigned aLd = sb + ((wm + (lane & 7) + ((lane >> 3) & 1) * 8) * STRA
                         + ((lane >> 4) & 1) * 8) * 2;
    unsigned bLd = sb + (AH + ((lane & 7) + ((lane >> 3) & 1) * 8) * BSTR
                         + wn + ((lane >> 4) & 1) * 8) * 2;

    stage(0, 0);      CP_COMMIT();
    stage(1, BK);     CP_COMMIT();
    stage(2, 2 * BK); CP_COMMIT();

    const int nch = HID / BK;             // 64
    int s = 0;
    for (int i = 0; i < nch; i++) {
        CP_WAIT2();
        __syncthreads();
        {
            int s3 = s + 3; if (s3 >= NST) s3 -= NST;
            if (i + 3 < nch) stage(s3, (i + 3) * BK);
        }
        CP_COMMIT();
        unsigned stOff = (unsigned)s * (STGH * 2);
        GEMM_CHUNK(stOff)
        s = (s + 1 == NST) ? 0 : s + 1;
    }
    __syncthreads();

    // ---- gate warps (wn<128) dump to smem; up warps fuse silu + store ----
    float* HSg = (float*)smh;             // [192][HSW] fp32, overlays stages
    if (wn < 128) {
#pragma unroll
        for (int mi = 0; mi < 4; mi++) {
            int rb = wm + mi * 16 + (lane >> 2);
#pragma unroll
            for (int ni = 0; ni < 8; ni++) {
                int cc = wn + ni * 8 + (lane & 3) * 2;
                HSg[rb * HSW + cc]           = acc[mi][ni][0];
                HSg[rb * HSW + cc + 1]       = acc[mi][ni][1];
                HSg[(rb + 8) * HSW + cc]     = acc[mi][ni][2];
                HSg[(rb + 8) * HSW + cc + 1] = acc[mi][ni][3];
            }
        }
    }
    __syncthreads();
    if (wn >= 128) {
        int nbase = wn - 128;
#pragma unroll
        for (int mi = 0; mi < 4; mi++) {
            int rb = wm + mi * 16 + (lane >> 2);
#pragma unroll
            for (int ni = 0; ni < 8; ni++) {
                int c = nbase + ni * 8 + (lane & 3) * 2;
#pragma unroll
                for (int h = 0; h < 2; h++) {
                    int r = rb + h * 8;
                    if (r < valid) {
                        float g0 = HSg[r * HSW + c], g1 = HSg[r * HSW + c + 1];
                        float u0 = acc[mi][ni][h * 2], u1 = acc[mi][ni][h * 2 + 1];
                        float h0 = g0 / (1.f + __expf(-g0)) * u0;
                        float h1 = g1 / (1.f + __expf(-g1)) * u1;
                        __half2 hp = __floats2half2_rn(h0, h1);
                        *(__half2*)(h_h + (size_t)(pbase + r) * IEXP + n0 + c) = hp;
                    }
                }
            }
        }
    }
}

// ============== down-proj: CTA 192m x 256n, row scatter ======================
__global__ __launch_bounds__(384, 1)
void k_down(float* __restrict__ out)
{
    extern __shared__ __half smh[];
    int e   = blockIdx.z;
    int cnt = cnt_d[e];
    int m0  = blockIdx.y * BM;
    if (m0 >= cnt) return;
    int n0    = blockIdx.x * 256;
    int valid = min(cnt - m0, BM);
    int pbase = base_d[e] + m0;
    int tid = threadIdx.x, lane = tid & 31, wid = tid >> 5;

    int* toks = (int*)((char*)smh + TOKS_OFF);
    if (tid < BM) toks[tid] = perm_d[pbase + min(tid, valid - 1)];
    __syncthreads();

    int arow = tid >> 1, aseg = tid & 1;
    const __half* Ag = h_h + (size_t)(pbase + min(arow, valid - 1)) * IEXP + aseg * 16;
    unsigned sb = (unsigned)__cvta_generic_to_shared(smh);
    unsigned aD = sb + (arow * STRA + aseg * 16) * 2;

    int brw = (tid & 255) >> 3, bsg = tid & 7;
    const __half* Dg = dw_h + (size_t)e * IEXP * HID + (size_t)brw * HID + n0 + bsg * 32;
    unsigned bD = sb + (AH + brw * BSTR + bsg * 32) * 2;
    bool doB = (tid < 256);

    auto stage = [&](int s, int k0) {
        unsigned off = (unsigned)s * (STGH * 2);
        const __half* as = Ag + k0;
        cp16(aD + off, as);
        cp16(aD + off + 16, as + 8);
        if (doB) {
            const __half* bs = Dg + (size_t)k0 * HID;
#pragma unroll
            for (int j = 0; j < 4; j++) cp16(bD + off + j * 16, bs + j * 8);
        }
    };

    float acc[4][8][4];
#pragma unroll
    for (int i = 0; i < 4; i++)
#pragma unroll
        for (int j = 0; j < 8; j++)
#pragma unroll
            for (int k = 0; k < 4; k++) acc[i][j][k] = 0.f;

    int wm = (wid % 3) * 64;
    int wn = (wid / 3) * 64;

    unsigned aLd = sb + ((wm + (lane & 7) + ((lane >> 3) & 1) * 8) * STRA
                         + ((lane >> 4) & 1) * 8) * 2;
    unsigned bLd = sb + (AH + ((lane & 7) + ((lane >> 3) & 1) * 8) * BSTR
                         + wn + ((lane >> 4) & 1) * 8) * 2;

    stage(0, 0);      CP_COMMIT();
    stage(1, BK);     CP_COMMIT();
    stage(2, 2 * BK); CP_COMMIT();

    const int nch = IEXP / BK;            // 32
    int s = 0;
    for (int i = 0; i < nch; i++) {
        CP_WAIT2();
        __syncthreads();
        {
            int s3 = s + 3; if (s3 >= NST) s3 -= NST;
            if (i + 3 < nch) stage(s3, (i + 3) * BK);
        }
        CP_COMMIT();
        unsigned stOff = (unsigned)s * (STGH * 2);
        GEMM_CHUNK(stOff)
        s = (s + 1 == NST) ? 0 : s + 1;
    }

    // scatter rows by token id
#pragma unroll
    for (int mi = 0; mi < 4; mi++) {
        int rb = wm + mi * 16 + (lane >> 2);
#pragma unroll
        for (int ni = 0; ni < 8; ni++) {
            int cc = n0 + wn + ni * 8 + (lane & 3) * 2;
#pragma unroll
            for (int h = 0; h < 2; h++) {
                int r = rb + h * 8;
                if (r < valid) {
                    float* row = out + (size_t)toks[r] * HID;
                    row[cc]     = acc[mi][ni][h * 2];
                    row[cc + 1] = acc[mi][ni][h * 2 + 1];
                }
            }
        }
    }
}

extern "C" void kernel_launch(void* const* d_in, const int* in_sizes, int n_in,
                              void* d_out, int out_size)
{
    const float* hs   = (const float*)d_in[0];
    const int*   ids  = (const int*)d_in[1];
    const float* gate = (const float*)d_in[2];
    const float* up   = (const float*)d_in[3];
    const float* down = (const float*)d_in[4];
    float*       out  = (float*)d_out;

    cudaFuncSetAttribute(k_mlp,  cudaFuncAttributeMaxDynamicSharedMemorySize, SMB);
    cudaFuncSetAttribute(k_down, cudaFuncAttributeMaxDynamicSharedMemorySize, SMB);

    k_route<<<1, 256>>>(ids);
    k_prep<<<(T_TOK * HID) / 2048, 256>>>(hs);
    k_wconv<<<dim3((NEXP * HID * IEXP) / 2048, 3), 256>>>(gate, up, down);
    // grid.y covers up to 22*192 = 4224 tokens per expert (48 sigma margin)
    k_mlp <<<dim3(IEXP / 128, 22, NEXP), 384, SMB>>>();
    k_down<<<dim3(HID / 256,  22, NEXP), 384, SMB>>>(out);
}